// round 13
// baseline (speedup 1.0000x reference)
#include <cuda_runtime.h>
#include <math_constants.h>

// RoIPool: feature_map [B=2, H=50, W=50, C=256] f32, rpn_pred [B=2, N=128, 4] f32
// out [B, N, 7, 7, C] f32.
//   x1=(int)(W*p0); y1=(int)(H*p1); x2=(int)(W*p2); y2=(int)(H*p3)
//   sw=(x2-x1)/7; sh=(y2-y1)/7   (in [1,4] by input construction)
//   out[b,n,i,j,c] = max_{r<sh,t<sw} fm[b, y1+i*sh+r, x1+j*sw+t, c]
// Bounds: x1+7*sw-1 <= x2-1 <= 49 (same for y) -> reference clip is dead code.
//
// R13: max-ILP + higher occupancy. Thread = 4 channels (ONE float4 acc),
// 64 threads per bin; CTA = 256 threads = 4 bins; grid (13,128,2) covers 52
// slots (3 phantoms alias bin 48, not stored). Window cells staged in chunks
// of EIGHT: all 8 LDG.128 issued before any fmax -> 77% of windows (<=8
// cells) take a SINGLE L2-latency exposure, rest take 2 (avg 1.23 vs R12's
// ~1.8). Staging = 32 regs -> ~52 total -> 4 CTAs/SM (32 warps, 42% occ).

#define POOL 7
#define NROIS 128
#define BB 2
#define HH 50
#define WW 50
#define CC 256
#define C4 (CC / 4)   // 64 float4 per pixel
#define NBINS (POOL * POOL)       // 49
#define THREADS 256               // 4 bins x 64 threads
#define NBLKX 13                  // ceil(52/4): 52 bin slots per ROI

__device__ __forceinline__ void fmax4(float4& m, const float4 v) {
    m.x = fmaxf(m.x, v.x);
    m.y = fmaxf(m.y, v.y);
    m.z = fmaxf(m.z, v.z);
    m.w = fmaxf(m.w, v.w);
}

// Exact SHxSW window, 1 float4 per cell per thread, chunks of 8 cells:
// all loads of a chunk issued before any consumption.
template<int SH, int SW>
__device__ __forceinline__ void window4(const float4* __restrict__ base,
                                        float4& acc) {
    constexpr int NCELL = SH * SW;
    constexpr int NCHUNK = (NCELL + 7) / 8;
    #pragma unroll
    for (int g = 0; g < NCHUNK; ++g) {
        float4 buf[8];
        // Issue phase: up to 8 independent LDG.128, compile-time offsets.
        #pragma unroll
        for (int u = 0; u < 8; ++u) {
            const int k = g * 8 + u;
            if (k < NCELL) {
                const int r = k / SW;
                const int t = k - r * SW;
                buf[u] = __ldg(base + (r * WW + t) * C4);
            }
        }
        // Consume phase.
        #pragma unroll
        for (int u = 0; u < 8; ++u) {
            const int k = g * 8 + u;
            if (k < NCELL) fmax4(acc, buf[u]);
        }
    }
}

__global__ __launch_bounds__(THREADS, 4) void roi_pool_kernel(
    const float4* __restrict__ fm,     // [B*H*W*C4] float4
    const float4* __restrict__ rois,   // [B*N] float4 (x1,y1,x2,y2)
    float4*       __restrict__ out)    // [B*N*49*C4] float4
{
    const int slot = threadIdx.x >> 6;          // 0..3 -> bin slot
    const int t64  = threadIdx.x & 63;          // 0..63 -> float4 channel idx

    const int n = blockIdx.y;
    const int b = blockIdx.z;

    const int bin   = blockIdx.x * 4 + slot;    // 0..51
    const bool valid = (bin < NBINS);
    const int binc  = valid ? bin : (NBINS - 1);  // phantom -> alias bin 48

    const float4 rp = __ldg(rois + b * NROIS + n);
    const int x1 = (int)(WW * rp.x);
    const int y1 = (int)(HH * rp.y);
    const int sw = ((int)(WW * rp.z) - x1) / POOL;   // in [1,4]
    const int sh = ((int)(HH * rp.w) - y1) / POOL;   // in [1,4]

    const int i = binc / POOL;
    const int j = binc - i * POOL;

    const float4* base =
        fm + ((b * HH + (y1 + i * sh)) * WW + (x1 + j * sw)) * C4 + t64;

    const float NEG = -CUDART_INF_F;
    float4 acc = make_float4(NEG, NEG, NEG, NEG);

    // CTA-uniform 16-way dispatch on (sh,sw).
    const int code = (sh - 1) * 4 + (sw - 1);
    switch (code) {
        case  0: window4<1,1>(base, acc); break;
        case  1: window4<1,2>(base, acc); break;
        case  2: window4<1,3>(base, acc); break;
        case  3: window4<1,4>(base, acc); break;
        case  4: window4<2,1>(base, acc); break;
        case  5: window4<2,2>(base, acc); break;
        case  6: window4<2,3>(base, acc); break;
        case  7: window4<2,4>(base, acc); break;
        case  8: window4<3,1>(base, acc); break;
        case  9: window4<3,2>(base, acc); break;
        case 10: window4<3,3>(base, acc); break;
        case 11: window4<3,4>(base, acc); break;
        case 12: window4<4,1>(base, acc); break;
        case 13: window4<4,2>(base, acc); break;
        case 14: window4<4,3>(base, acc); break;
        default: window4<4,4>(base, acc); break;
    }

    if (valid) {
        out[((b * NROIS + n) * NBINS + bin) * C4 + t64] = acc;
    }
}

extern "C" void kernel_launch(void* const* d_in, const int* in_sizes, int n_in,
                              void* d_out, int out_size) {
    const float4* fm   = (const float4*)d_in[0];  // feature_map
    const float4* rois = (const float4*)d_in[1];  // rpn_pred as float4
    float4*       out  = (float4*)d_out;

    dim3 grid(NBLKX, NROIS, BB);                  // 13 x 128 x 2 = 3328 CTAs
    roi_pool_kernel<<<grid, THREADS>>>(fm, rois, out);
}